// round 2
// baseline (speedup 1.0000x reference)
#include <cuda_runtime.h>
#include <cuda_fp16.h>
#include <cstdint>

// Problem dimensions (fixed by the dataset)
#define M_DIM 1024
#define K_DIM 4096
#define N_DIM 4096
#define PACK  8        // int32 holds 8 x 4-bit values

// Device-global scratch (no allocation allowed).
__device__ __half g_Wd[(size_t)K_DIM * N_DIM];   // dequantized W, fp16 [K, N]: 32 MB
__device__ __half g_Xh[(size_t)M_DIM * K_DIM];   // x converted to fp16 [M, K]: 8 MB

// ---------------------------------------------------------------------------
// Kernel 0: convert x (stored as float32 by harness) -> fp16. Lossless:
// original data was fp16.
// ---------------------------------------------------------------------------
__global__ void convert_x_kernel(const float* __restrict__ x) {
    int idx = blockIdx.x * blockDim.x + threadIdx.x;
    int total = M_DIM * K_DIM;
    if (idx * 4 >= total) return;
    float4 v = reinterpret_cast<const float4*>(x)[idx];
    __half2 h0 = __floats2half2_rn(v.x, v.y);
    __half2 h1 = __floats2half2_rn(v.z, v.w);
    reinterpret_cast<__half2*>(g_Xh)[idx * 2]     = h0;
    reinterpret_cast<__half2*>(g_Xh)[idx * 2 + 1] = h1;
}

// ---------------------------------------------------------------------------
// Kernel 1: GPTQ 4-bit dequantize -> fp16 dense W [K, N]
// qweight: int32 [K/8, N]  (packed along K)
// qzeros : int32 [G, N/8]  (packed along N)
// scales : float32 [G, N]  (harness-upcast from fp16)
// g_idx  : int32 [K]
// w = scale * (q - (z + 1))
// ---------------------------------------------------------------------------
__global__ void dequant_kernel(const int* __restrict__ qweight,
                               const float* __restrict__ scales,
                               const int* __restrict__ qzeros,
                               const int* __restrict__ g_idx) {
    int idx = blockIdx.x * blockDim.x + threadIdx.x;   // over (K/8)*N
    if (idx >= (K_DIM / PACK) * N_DIM) return;
    int n  = idx % N_DIM;
    int kp = idx / N_DIM;

    uint32_t qw = (uint32_t)qweight[(size_t)kp * N_DIM + n];
    int k0 = kp * PACK;
    int nz_col = n / PACK;
    int nz_sh  = (n % PACK) * 4;

    // All 8 K-positions in this pack share one group (GS=128, 8 | 128),
    // but read per-element for generality; L1 broadcasts.
#pragma unroll
    for (int i = 0; i < PACK; i++) {
        int g = g_idx[k0 + i];
        uint32_t zw = (uint32_t)qzeros[(size_t)g * (N_DIM / PACK) + nz_col];
        float z = (float)((zw >> nz_sh) & 0xF) + 1.0f;
        float s = scales[(size_t)g * N_DIM + n];
        float q = (float)((qw >> (i * 4)) & 0xF);
        g_Wd[(size_t)(k0 + i) * N_DIM + n] = __float2half(s * (q - z));
    }
}

// ---------------------------------------------------------------------------
// Kernel 2: fp16 GEMM with mma.sync m16n8k16, cp.async double buffering.
// C[M,N] fp32 = Xh[M,K] fp16 @ W[K,N] fp16 + bias(f32)
// Block tile 128x128x32, 8 warps (2 m x 4 n), warp tile 64x32.
// ---------------------------------------------------------------------------
#define BM 128
#define BN 128
#define BK 32
#define PAD_A 8
#define PAD_B 8

__device__ __forceinline__ void cp_async16(void* smem, const void* gmem) {
    uint32_t s = (uint32_t)__cvta_generic_to_shared(smem);
    asm volatile("cp.async.cg.shared.global [%0], [%1], 16;\n" :: "r"(s), "l"(gmem));
}
__device__ __forceinline__ void cp_commit() {
    asm volatile("cp.async.commit_group;\n" ::: "memory");
}
__device__ __forceinline__ void cp_wait0() {
    asm volatile("cp.async.wait_group 0;\n" ::: "memory");
}

__device__ __forceinline__ void ldsm_x4(uint32_t& r0, uint32_t& r1,
                                        uint32_t& r2, uint32_t& r3,
                                        const void* p) {
    uint32_t s = (uint32_t)__cvta_generic_to_shared(p);
    asm volatile("ldmatrix.sync.aligned.m8n8.x4.shared.b16 {%0,%1,%2,%3}, [%4];\n"
                 : "=r"(r0), "=r"(r1), "=r"(r2), "=r"(r3) : "r"(s));
}
__device__ __forceinline__ void ldsm_x4_trans(uint32_t& r0, uint32_t& r1,
                                              uint32_t& r2, uint32_t& r3,
                                              const void* p) {
    uint32_t s = (uint32_t)__cvta_generic_to_shared(p);
    asm volatile("ldmatrix.sync.aligned.m8n8.x4.trans.shared.b16 {%0,%1,%2,%3}, [%4];\n"
                 : "=r"(r0), "=r"(r1), "=r"(r2), "=r"(r3) : "r"(s));
}
__device__ __forceinline__ void mma_16816(float& c0, float& c1, float& c2, float& c3,
                                          uint32_t a0, uint32_t a1, uint32_t a2, uint32_t a3,
                                          uint32_t b0, uint32_t b1) {
    asm volatile(
        "mma.sync.aligned.m16n8k16.row.col.f32.f16.f16.f32 "
        "{%0,%1,%2,%3}, {%4,%5,%6,%7}, {%8,%9}, {%0,%1,%2,%3};\n"
        : "+f"(c0), "+f"(c1), "+f"(c2), "+f"(c3)
        : "r"(a0), "r"(a1), "r"(a2), "r"(a3), "r"(b0), "r"(b1));
}

__global__ __launch_bounds__(256, 1)
void gemm_kernel(const float* __restrict__ bias,  // [N] fp32
                 float* __restrict__ C) {         // [M, N] fp32
    __shared__ __align__(16) __half As[2][BM][BK + PAD_A];
    __shared__ __align__(16) __half Bs[2][BK][BN + PAD_B];

    const int tid  = threadIdx.x;
    const int lane = tid & 31;
    const int warp = tid >> 5;
    const int warp_m = warp >> 2;   // 0..1
    const int warp_n = warp & 3;    // 0..3

    const int n_block = blockIdx.x * BN;
    const int m_block = blockIdx.y * BM;

    const __half* A  = g_Xh;
    const __half* Wd = g_Wd;

    float acc[4][4][4];   // [mi][ni][4]
#pragma unroll
    for (int mi = 0; mi < 4; mi++)
#pragma unroll
        for (int ni = 0; ni < 4; ni++)
#pragma unroll
            for (int r = 0; r < 4; r++) acc[mi][ni][r] = 0.0f;

    // --- tile loaders: 512 chunks of 16B each, 2 per thread ---
    auto load_A = [&](int buf, int kt) {
#pragma unroll
        for (int r = 0; r < 2; r++) {
            int ch  = tid + r * 256;
            int row = ch >> 2;            // 0..127
            int col = (ch & 3) * 8;       // 0,8,16,24
            cp_async16(&As[buf][row][col],
                       A + (size_t)(m_block + row) * K_DIM + kt * BK + col);
        }
    };
    auto load_B = [&](int buf, int kt) {
#pragma unroll
        for (int r = 0; r < 2; r++) {
            int ch  = tid + r * 256;
            int row = ch >> 4;            // 0..31
            int col = (ch & 15) * 8;      // 0..120
            cp_async16(&Bs[buf][row][col],
                       Wd + (size_t)(kt * BK + row) * N_DIM + n_block + col);
        }
    };

    const int KT = K_DIM / BK;   // 128

    load_A(0, 0);
    load_B(0, 0);
    cp_commit();
    cp_wait0();
    __syncthreads();

    int buf = 0;
    for (int kt = 0; kt < KT; kt++) {
        if (kt + 1 < KT) {
            load_A(buf ^ 1, kt + 1);
            load_B(buf ^ 1, kt + 1);
            cp_commit();
        }

#pragma unroll
        for (int ks = 0; ks < BK; ks += 16) {
            uint32_t a[4][4];
            uint32_t b[4][2];
            // A fragments: 4 x m16 tiles at warp_m*64
            const int ar = lane & 15;
            const int ac = (lane >> 4) * 8;
#pragma unroll
            for (int mi = 0; mi < 4; mi++) {
                ldsm_x4(a[mi][0], a[mi][1], a[mi][2], a[mi][3],
                        &As[buf][warp_m * 64 + mi * 16 + ar][ks + ac]);
            }
            // B fragments: 2 x (16k x 16n) trans loads -> 4 n8 fragments
            const int br = lane & 15;
            const int bc = (lane >> 4) * 8;
#pragma unroll
            for (int nb = 0; nb < 2; nb++) {
                ldsm_x4_trans(b[2 * nb][0], b[2 * nb][1],
                              b[2 * nb + 1][0], b[2 * nb + 1][1],
                              &Bs[buf][ks + br][warp_n * 32 + nb * 16 + bc]);
            }
#pragma unroll
            for (int mi = 0; mi < 4; mi++)
#pragma unroll
                for (int ni = 0; ni < 4; ni++)
                    mma_16816(acc[mi][ni][0], acc[mi][ni][1],
                              acc[mi][ni][2], acc[mi][ni][3],
                              a[mi][0], a[mi][1], a[mi][2], a[mi][3],
                              b[ni][0], b[ni][1]);
        }

        if (kt + 1 < KT) cp_wait0();
        __syncthreads();
        buf ^= 1;
    }

    // --- epilogue: fp32 store + bias (fp32) ---
    const int m_base = m_block + warp_m * 64;
    const int n_base = n_block + warp_n * 32;
    const int lr = lane >> 2;         // 0..7
    const int lc = (lane & 3) * 2;    // 0,2,4,6

#pragma unroll
    for (int ni = 0; ni < 4; ni++) {
        const int ncol = n_base + ni * 8 + lc;
        const float b0 = bias[ncol];
        const float b1 = bias[ncol + 1];
#pragma unroll
        for (int mi = 0; mi < 4; mi++) {
            float* o0 = C + (size_t)(m_base + mi * 16 + lr) * N_DIM + ncol;
            float* o1 = C + (size_t)(m_base + mi * 16 + lr + 8) * N_DIM + ncol;
            float2 v0 = make_float2(acc[mi][ni][0] + b0, acc[mi][ni][1] + b1);
            float2 v1 = make_float2(acc[mi][ni][2] + b0, acc[mi][ni][3] + b1);
            *reinterpret_cast<float2*>(o0) = v0;
            *reinterpret_cast<float2*>(o1) = v1;
        }
    }
}

// ---------------------------------------------------------------------------
// kernel_launch
// inputs (metadata order): x[f32], qweight[int32], scales[f32],
//                          qzeros[int32], g_idx[int32], bias[f32]
// (fp16 arrays in the reference are materialized as float32 by the harness)
// output: float32 [M, N]
// ---------------------------------------------------------------------------
extern "C" void kernel_launch(void* const* d_in, const int* in_sizes, int n_in,
                              void* d_out, int out_size) {
    const float* x       = (const float*)d_in[0];
    const int*   qweight = (const int*)d_in[1];
    const float* scales  = (const float*)d_in[2];
    const int*   qzeros  = (const int*)d_in[3];
    const int*   g_idx   = (const int*)d_in[4];
    const float* bias    = (const float*)d_in[5];
    float* out = (float*)d_out;

    // 0) convert x (f32) -> fp16 device global
    {
        int total4 = (M_DIM * K_DIM) / 4;
        convert_x_kernel<<<(total4 + 255) / 256, 256>>>(x);
    }

    // 1) dequantize to fp16 dense W in device global
    {
        int total = (K_DIM / PACK) * N_DIM;      // 2,097,152
        dequant_kernel<<<(total + 255) / 256, 256>>>(qweight, scales, qzeros, g_idx);
    }

    // 2) GEMM + bias
    {
        dim3 grid(N_DIM / BN, M_DIM / BM);       // (32, 8)
        gemm_kernel<<<grid, 256>>>(bias, out);
    }
}

// round 4
// speedup vs baseline: 1.6782x; 1.6782x over previous
#include <cuda_runtime.h>
#include <cuda_fp16.h>
#include <cstdint>

#define M_DIM 1024
#define K_DIM 4096
#define N_DIM 4096

// x as fp16 [M, K], with k-permutation {0,4,1,5,2,6,3,7} within each 8-block
// (matches the order the fused dequant produces for B).
__device__ __half g_Xh[(size_t)M_DIM * K_DIM];

// ---------------------------------------------------------------------------
// Kernel 0: x (f32) -> fp16, permuted k within each 8-group.
// Thread reads 8 consecutive floats (k0..k7), writes half2 pairs
// (k0,k4),(k1,k5),(k2,k6),(k3,k7) as one 16B store.
// ---------------------------------------------------------------------------
__global__ void convert_x_kernel(const float* __restrict__ x) {
    int idx = blockIdx.x * blockDim.x + threadIdx.x;       // per 8 floats
    if (idx >= (M_DIM * K_DIM) / 8) return;
    const float4 v0 = reinterpret_cast<const float4*>(x)[idx * 2];
    const float4 v1 = reinterpret_cast<const float4*>(x)[idx * 2 + 1];
    __half2 h[4];
    h[0] = __floats2half2_rn(v0.x, v1.x);   // (k0, k4)
    h[1] = __floats2half2_rn(v0.y, v1.y);   // (k1, k5)
    h[2] = __floats2half2_rn(v0.z, v1.z);   // (k2, k6)
    h[3] = __floats2half2_rn(v0.w, v1.w);   // (k3, k7)
    reinterpret_cast<uint4*>(g_Xh)[idx] = *reinterpret_cast<const uint4*>(h);
}

// ---------------------------------------------------------------------------
// Fused dequant + GEMM.
// C[M,N] = Xh[M,K] @ W[K,N] + bias, W dequantized from 4-bit on the fly.
// Tile BM=128 x BN=128 x BK=64, 8 warps (2m x 4n), warp tile 64x32.
// A: cp.async fp16.  B: qweight words -> fp16 SMEM [n][k] (k contiguous).
// 2-stage SMEM double buffer + register prefetch of next B words.
// ---------------------------------------------------------------------------
#define BM 128
#define BN 128
#define BK 64
#define PADK 8                       // halfs of padding per row
#define ROWB ((BK + PADK) * 2)       // 144 bytes per SMEM row
#define STAGE_BYTES (128 * ROWB)     // 18432 per operand per stage
#define KT_ITERS (K_DIM / BK)        // 64

__device__ __forceinline__ void cp_async16(uint32_t smem, const void* gmem) {
    asm volatile("cp.async.cg.shared.global [%0], [%1], 16;\n" :: "r"(smem), "l"(gmem));
}
__device__ __forceinline__ void cp_commit() {
    asm volatile("cp.async.commit_group;\n" ::: "memory");
}
__device__ __forceinline__ void cp_wait0() {
    asm volatile("cp.async.wait_group 0;\n" ::: "memory");
}
__device__ __forceinline__ uint32_t smem_u32(const void* p) {
    uint32_t a;
    asm("{ .reg .u64 t; cvta.to.shared.u64 t, %1; cvt.u32.u64 %0, t; }" : "=r"(a) : "l"(p));
    return a;
}
__device__ __forceinline__ void ldsm_x4(uint32_t& r0, uint32_t& r1,
                                        uint32_t& r2, uint32_t& r3, uint32_t s) {
    asm volatile("ldmatrix.sync.aligned.m8n8.x4.shared.b16 {%0,%1,%2,%3}, [%4];\n"
                 : "=r"(r0), "=r"(r1), "=r"(r2), "=r"(r3) : "r"(s));
}
__device__ __forceinline__ void mma_16816(float& c0, float& c1, float& c2, float& c3,
                                          uint32_t a0, uint32_t a1, uint32_t a2, uint32_t a3,
                                          uint32_t b0, uint32_t b1) {
    asm volatile(
        "mma.sync.aligned.m16n8k16.row.col.f32.f16.f16.f32 "
        "{%0,%1,%2,%3}, {%4,%5,%6,%7}, {%8,%9}, {%0,%1,%2,%3};\n"
        : "+f"(c0), "+f"(c1), "+f"(c2), "+f"(c3)
        : "r"(a0), "r"(a1), "r"(a2), "r"(a3), "r"(b0), "r"(b1));
}

__global__ __launch_bounds__(256, 2)
void gemm_fused_kernel(const int* __restrict__ qweight,    // [K/8, N]
                       const float* __restrict__ scales,   // [G, N]
                       const int* __restrict__ qzeros,     // [G, N/8]
                       const int* __restrict__ g_idx,      // [K]
                       const float* __restrict__ bias,     // [N]
                       float* __restrict__ C) {            // [M, N]
    extern __shared__ __align__(128) char smem[];
    const uint32_t sbase = smem_u32(smem);
    const uint32_t As_base = sbase;                        // 2 stages A
    const uint32_t Bs_base = sbase + 2 * STAGE_BYTES;      // 2 stages B

    const int tid  = threadIdx.x;
    const int lane = tid & 31;
    const int warp = tid >> 5;
    const int warp_m = warp >> 2;     // 0..1
    const int warp_n = warp & 3;      // 0..3

    const int n0 = blockIdx.x * BN;
    const int m0 = blockIdx.y * BM;

    const __half* Abase = g_Xh + (size_t)m0 * K_DIM;

    // ---- B dequant thread mapping: fixed n per thread, 4 word-rows per stage
    const int nloc  = tid & 127;          // 0..127  (n within tile)
    const int rbase = tid >> 7;           // 0 or 1
    const int n_g   = n0 + nloc;          // global n
    const int zsh   = (n_g & 7) * 4;
    const int zcol  = n_g >> 3;

    float acc[4][4][4];
#pragma unroll
    for (int mi = 0; mi < 4; mi++)
#pragma unroll
        for (int ni = 0; ni < 4; ni++)
#pragma unroll
            for (int r = 0; r < 4; r++) acc[mi][ni][r] = 0.0f;

    // ---- helpers ----
    auto load_A_async = [&](int buf, int kt) {
        const uint32_t As = As_base + buf * STAGE_BYTES;
        const __half* Ag = Abase + kt * BK;
#pragma unroll
        for (int i = 0; i < 4; i++) {                 // 1024 chunks / 256 thr
            int q = tid + i * 256;
            int r = q >> 3, ch = q & 7;
            cp_async16(As + r * ROWB + ch * 16, Ag + (size_t)r * K_DIM + ch * 8);
        }
    };
    auto fetch_B = [&](int kt, uint32_t qn[4], float& s, uint32_t& zw) {
        const int g = g_idx[kt * BK];                 // uniform within stage (GS=128)
        s  = scales[(size_t)g * N_DIM + n_g];
        zw = (uint32_t)qzeros[(size_t)g * (N_DIM / 8) + zcol];
#pragma unroll
        for (int i = 0; i < 4; i++) {
            int kp = kt * 8 + rbase + 2 * i;
            qn[i] = (uint32_t)qweight[(size_t)kp * N_DIM + n_g];
        }
    };
    auto store_B = [&](int buf, const uint32_t qn[4], float s, uint32_t zw) {
        const uint32_t Bs = Bs_base + buf * STAGE_BYTES;
        const int z = (int)((zw >> zsh) & 0xF);
        const __half2 hz2 = __half2half2(__int2half_rn(1025 + z));
        const __half2 s2  = __half2half2(__float2half_rn(s));
#pragma unroll
        for (int i = 0; i < 4; i++) {
            const uint32_t w = qn[i];
            uint32_t p0 = (w & 0x000F000Fu) | 0x64006400u;          // (q0,q4)+1024
            uint32_t p1 = ((w >> 4) & 0x000F000Fu) | 0x64006400u;   // (q1,q5)+1024
            uint32_t p2 = ((w >> 8) & 0x000F000Fu) | 0x64006400u;   // (q2,q6)+1024
            uint32_t p3 = ((w >> 12) & 0x000F000Fu) | 0x64006400u;  // (q3,q7)+1024
            __half2 v[4];
            v[0] = __hmul2(__hsub2(*(__half2*)&p0, hz2), s2);
            v[1] = __hmul2(__hsub2(*(__half2*)&p1, hz2), s2);
            v[2] = __hmul2(__hsub2(*(__half2*)&p2, hz2), s2);
            v[3] = __hmul2(__hsub2(*(__half2*)&p3, hz2), s2);
            const int r = rbase + 2 * i;              // local k-block 0..7
            *reinterpret_cast<uint4*>(smem + (Bs - sbase) + nloc * ROWB + r * 16) =
                *reinterpret_cast<const uint4*>(v);
        }
    };

    // ---- prologue: stage 0 ----
    {
        uint32_t q0[4]; float s0; uint32_t zw0;
        fetch_B(0, q0, s0, zw0);
        load_A_async(0, 0);
        cp_commit();
        store_B(0, q0, s0, zw0);
        cp_wait0();
        __syncthreads();
    }

    // ---- main loop ----
    for (int kt = 0; kt < KT_ITERS; kt++) {
        const int buf = kt & 1;
        const bool has_next = (kt + 1 < KT_ITERS);

        uint32_t qn[4]; float sn; uint32_t zwn;
        if (has_next) {
            fetch_B(kt + 1, qn, sn, zwn);     // LDGs overlap the mma below
            load_A_async(buf ^ 1, kt + 1);
            cp_commit();
        }

        // compute on current buffers
        const uint32_t Asb = As_base + buf * STAGE_BYTES;
        const uint32_t Bsb = Bs_base + buf * STAGE_BYTES;
#pragma unroll
        for (int ks = 0; ks < BK; ks += 16) {
            uint32_t a[4][4];
            uint32_t b[4][2];
            const int ar = lane & 15;
            const int ac = (lane >> 4) * 8;
#pragma unroll
            for (int mi = 0; mi < 4; mi++)
                ldsm_x4(a[mi][0], a[mi][1], a[mi][2], a[mi][3],
                        Asb + (warp_m * 64 + mi * 16 + ar) * ROWB + (ks + ac) * 2);
            // B: non-trans ldmatrix on [n][k] tiles
            const int brow = (lane & 7) + ((lane >> 4) << 3);   // n offset 0..15
            const int bcol = ((lane >> 3) & 1) * 8;             // k offset 0/8
#pragma unroll
            for (int nb = 0; nb < 2; nb++)
                ldsm_x4(b[2 * nb][0], b[2 * nb][1], b[2 * nb + 1][0], b[2 * nb + 1][1],
                        Bsb + (warp_n * 32 + nb * 16 + brow) * ROWB + (ks + bcol) * 2);
#pragma unroll
            for (int mi = 0; mi < 4; mi++)
#pragma unroll
                for (int ni = 0; ni < 4; ni++)
                    mma_16816(acc[mi][ni][0], acc[mi][ni][1],
                              acc[mi][ni][2], acc[mi][ni][3],
                              a[mi][0], a[mi][1], a[mi][2], a[mi][3],
                              b[ni][0], b[ni][1]);
        }

        if (has_next) {
            cp_wait0();
            __syncthreads();                  // everyone done reading buf^1 (iter kt-1)
            store_B(buf ^ 1, qn, sn, zwn);
            __syncthreads();                  // B writes visible for iter kt+1
        }
    }

    // ---- epilogue: fp32 + bias ----
    const int m_base = m0 + warp_m * 64;
    const int n_base = n0 + warp_n * 32;
    const int lr = lane >> 2;
    const int lc = (lane & 3) * 2;

#pragma unroll
    for (int ni = 0; ni < 4; ni++) {
        const int ncol = n_base + ni * 8 + lc;
        const float b0 = bias[ncol];
        const float b1 = bias[ncol + 1];
#pragma unroll
        for (int mi = 0; mi < 4; mi++) {
            float* o0 = C + (size_t)(m_base + mi * 16 + lr) * N_DIM + ncol;
            float* o1 = C + (size_t)(m_base + mi * 16 + lr + 8) * N_DIM + ncol;
            *reinterpret_cast<float2*>(o0) =
                make_float2(acc[mi][ni][0] + b0, acc[mi][ni][1] + b1);
            *reinterpret_cast<float2*>(o1) =
                make_float2(acc[mi][ni][2] + b0, acc[mi][ni][3] + b1);
        }
    }
}

// ---------------------------------------------------------------------------
// kernel_launch
// inputs: x[f32], qweight[i32], scales[f32], qzeros[i32], g_idx[i32], bias[f32]
// output: float32 [M, N]
// ---------------------------------------------------------------------------
extern "C" void kernel_launch(void* const* d_in, const int* in_sizes, int n_in,
                              void* d_out, int out_size) {
    const float* x       = (const float*)d_in[0];
    const int*   qweight = (const int*)d_in[1];
    const float* scales  = (const float*)d_in[2];
    const int*   qzeros  = (const int*)d_in[3];
    const int*   g_idx   = (const int*)d_in[4];
    const float* bias    = (const float*)d_in[5];
    float* out = (float*)d_out;

    {
        int total = (M_DIM * K_DIM) / 8;
        convert_x_kernel<<<(total + 255) / 256, 256>>>(x);
    }
    {
        constexpr int SMEM_TOTAL = 4 * STAGE_BYTES;      // 73728 B
        cudaFuncSetAttribute(gemm_fused_kernel,
                             cudaFuncAttributeMaxDynamicSharedMemorySize, SMEM_TOTAL);
        dim3 grid(N_DIM / BN, M_DIM / BM);               // (32, 8)
        gemm_fused_kernel<<<grid, 256, SMEM_TOTAL>>>(qweight, scales, qzeros,
                                                     g_idx, bias, out);
    }
}